// round 1
// baseline (speedup 1.0000x reference)
#include <cuda_runtime.h>
#include <math.h>

// ---------------- problem constants ----------------
#define TT 1024     // tokens
#define EE 1024     // embed dim
#define VV 32000    // vocab
#define NH 16       // query heads
#define NKV 4       // kv heads
#define DHD 64      // head dim
#define KVD (NKV*DHD)   // 256
#define LNUM 2
#define RNUM 2
#define FF 4096
#define EPSV 1e-5f

// ---------------- device scratch (no allocations allowed) ----------------
__device__ float g_x[TT*EE];
__device__ float g_h[TT*EE];
__device__ float g_q[TT*EE];
__device__ float g_k[TT*KVD];
__device__ float g_v[TT*KVD];
__device__ float g_att[(size_t)NH*TT*TT];
__device__ float g_y[TT*EE];
__device__ float g_ff[TT*FF];
__device__ float g_logits[(size_t)TT*VV];
__device__ float g_loss;

// ---------------- helpers ----------------
__device__ __forceinline__ float blk_sum256(float v, float* sh) {
    int tid = threadIdx.x;
    sh[tid] = v; __syncthreads();
    #pragma unroll
    for (int s = 128; s > 0; s >>= 1) {
        if (tid < s) sh[tid] += sh[tid + s];
        __syncthreads();
    }
    float r = sh[0]; __syncthreads();
    return r;
}
__device__ __forceinline__ float blk_max256(float v, float* sh) {
    int tid = threadIdx.x;
    sh[tid] = v; __syncthreads();
    #pragma unroll
    for (int s = 128; s > 0; s >>= 1) {
        if (tid < s) sh[tid] = fmaxf(sh[tid], sh[tid + s]);
        __syncthreads();
    }
    float r = sh[0]; __syncthreads();
    return r;
}
__device__ __forceinline__ float gelu_exact(float x) {
    return 0.5f * x * (1.0f + erff(x * 0.7071067811865476f));
}

// ---------------- embedding gather ----------------
__global__ void gather_embed_k(const float* __restrict__ embed, const int* __restrict__ idx) {
    int i = blockIdx.x * blockDim.x + threadIdx.x;   // grid covers TT*EE
    int t = i >> 10;
    int e = i & 1023;
    g_x[i] = embed[(size_t)idx[t] * EE + e];
}

// ---------------- layernorm: one block per row ----------------
__global__ void layernorm_k(const float* __restrict__ in, float* __restrict__ out,
                            const float* __restrict__ g, const float* __restrict__ b) {
    __shared__ float sh[256];
    int row = blockIdx.x;
    const float* x = in + (size_t)row * EE;
    float s = 0.f;
    for (int i = threadIdx.x; i < EE; i += 256) s += x[i];
    float mu = blk_sum256(s, sh) * (1.0f / EE);
    float vs = 0.f;
    for (int i = threadIdx.x; i < EE; i += 256) { float d = x[i] - mu; vs += d * d; }
    float var = blk_sum256(vs, sh) * (1.0f / EE);
    float inv = rsqrtf(var + EPSV);
    float* o = out + (size_t)row * EE;
    for (int i = threadIdx.x; i < EE; i += 256)
        o[i] = (x[i] - mu) * inv * g[i] + b[i];
}

// ---------------- 128x128x8 SGEMM (fp32), MODE: 0=store 1=+resid 2=gelu ----------------
// TRANSB=false: B is [K,N] row-major. TRANSB=true: B is [N,K] row-major (C = A * B^T).
// All M,N divisible by 128, K by 8 in this problem.
template<int MODE, bool TRANSB>
__global__ __launch_bounds__(256) void sgemm_k(const float* __restrict__ A,
                                               const float* __restrict__ Bm,
                                               float* __restrict__ C,
                                               const float* __restrict__ Rs,
                                               int M, int N, int K) {
    __shared__ __align__(16) float As[8][132];
    __shared__ __align__(16) float Bs[8][132];
    const int tid = threadIdx.x;
    const int tx = tid & 15;
    const int ty = tid >> 4;
    const int bx = blockIdx.x, by = blockIdx.y;
    const int row0 = by * 128, col0 = bx * 128;

    float acc[8][8];
    #pragma unroll
    for (int i = 0; i < 8; i++)
        #pragma unroll
        for (int j = 0; j < 8; j++) acc[i][j] = 0.f;

    const int ar = tid >> 1;          // 0..127
    const int ak = (tid & 1) * 4;     // 0 or 4
    const int br = tid >> 5;          // 0..7
    const int bc = (tid & 31) * 4;    // 0..124

    for (int k0 = 0; k0 < K; k0 += 8) {
        float4 av = *(const float4*)(A + (size_t)(row0 + ar) * K + k0 + ak);
        As[ak + 0][ar] = av.x; As[ak + 1][ar] = av.y;
        As[ak + 2][ar] = av.z; As[ak + 3][ar] = av.w;
        if (!TRANSB) {
            float4 bv = *(const float4*)(Bm + (size_t)(k0 + br) * N + col0 + bc);
            *(float4*)&Bs[br][bc] = bv;
        } else {
            float4 bv = *(const float4*)(Bm + (size_t)(col0 + ar) * K + k0 + ak);
            Bs[ak + 0][ar] = bv.x; Bs[ak + 1][ar] = bv.y;
            Bs[ak + 2][ar] = bv.z; Bs[ak + 3][ar] = bv.w;
        }
        __syncthreads();
        #pragma unroll
        for (int kk = 0; kk < 8; kk++) {
            float a[8], b[8];
            *(float4*)&a[0] = *(float4*)&As[kk][ty * 4];
            *(float4*)&a[4] = *(float4*)&As[kk][64 + ty * 4];
            *(float4*)&b[0] = *(float4*)&Bs[kk][tx * 4];
            *(float4*)&b[4] = *(float4*)&Bs[kk][64 + tx * 4];
            #pragma unroll
            for (int i = 0; i < 8; i++)
                #pragma unroll
                for (int j = 0; j < 8; j++)
                    acc[i][j] += a[i] * b[j];
        }
        __syncthreads();
    }

    #pragma unroll
    for (int ig = 0; ig < 2; ig++) {
        #pragma unroll
        for (int i = 0; i < 4; i++) {
            int r = row0 + ig * 64 + ty * 4 + i;
            #pragma unroll
            for (int jg = 0; jg < 2; jg++) {
                int c = col0 + jg * 64 + tx * 4;
                float4 o;
                o.x = acc[ig * 4 + i][jg * 4 + 0];
                o.y = acc[ig * 4 + i][jg * 4 + 1];
                o.z = acc[ig * 4 + i][jg * 4 + 2];
                o.w = acc[ig * 4 + i][jg * 4 + 3];
                if (MODE == 1) {
                    float4 rv = *(const float4*)(Rs + (size_t)r * N + c);
                    o.x += rv.x; o.y += rv.y; o.z += rv.z; o.w += rv.w;
                } else if (MODE == 2) {
                    o.x = gelu_exact(o.x); o.y = gelu_exact(o.y);
                    o.z = gelu_exact(o.z); o.w = gelu_exact(o.w);
                }
                *(float4*)(C + (size_t)r * N + c) = o;
            }
        }
    }
}

// ---------------- RoPE (in-place, first 32 dims of each head) ----------------
__global__ void rope_k(float* __restrict__ buf, int nheads) {
    int i = blockIdx.x * blockDim.x + threadIdx.x;   // TT * nheads * 16
    int total = TT * nheads * 16;
    if (i >= total) return;
    int j = i & 15;
    int head = (i >> 4) % nheads;
    int t = i / (16 * nheads);
    float theta = powf(10000.0f, -(float)(2 * j) / 32.0f);
    float ang = (float)t * theta;
    float c = cosf(ang), s = sinf(ang);
    float* base = buf + (size_t)t * nheads * DHD + head * DHD;
    float x1 = base[j], x2 = base[j + 16];
    base[j]      = x1 * c - x2 * s;
    base[j + 16] = x2 * c + x1 * s;
}

// ---------------- attention scores: 64x64 tile per block, causal block-skip ----------------
__global__ __launch_bounds__(256) void attn_scores_k() {
    int st = blockIdx.x, tt = blockIdx.y, h = blockIdx.z;
    if (st > tt) return;   // entire tile above diagonal
    int kh = h >> 2;
    __shared__ float Qs[64][65];
    __shared__ float Ks[64][65];
    int tid = threadIdx.x;
    #pragma unroll
    for (int i = 0; i < 16; i++) {
        int idx = tid + i * 256;
        int r = idx >> 6, c = idx & 63;
        Qs[r][c] = g_q[(size_t)(tt * 64 + r) * EE + h * 64 + c];
        Ks[r][c] = g_k[(size_t)(st * 64 + r) * KVD + kh * 64 + c];
    }
    __syncthreads();
    int tx = tid & 15, ty = tid >> 4;
    float acc[4][4] = {};
    #pragma unroll 8
    for (int d = 0; d < 64; d++) {
        float a[4], b[4];
        #pragma unroll
        for (int i = 0; i < 4; i++) a[i] = Qs[ty * 4 + i][d];
        #pragma unroll
        for (int j = 0; j < 4; j++) b[j] = Ks[tx * 4 + j][d];
        #pragma unroll
        for (int i = 0; i < 4; i++)
            #pragma unroll
            for (int j = 0; j < 4; j++)
                acc[i][j] += a[i] * b[j];
    }
    #pragma unroll
    for (int i = 0; i < 4; i++)
        #pragma unroll
        for (int j = 0; j < 4; j++)
            g_att[(size_t)h * TT * TT + (size_t)(tt * 64 + ty * 4 + i) * TT + st * 64 + tx * 4 + j]
                = acc[i][j] * 0.125f;
}

// ---------------- row softmax + sigmoid-threshold gate, zero-fill s>t ----------------
__global__ void softmax_thresh_k(const float* __restrict__ gate_all, int l) {
    __shared__ float sh[256];
    int h = blockIdx.x >> 10;
    int t = blockIdx.x & 1023;
    float* p = g_att + (size_t)h * TT * TT + (size_t)t * TT;
    float thr = 1.0f / (1.0f + expf(-gate_all[l * NH + h]));
    float m = -1e30f;
    for (int i = threadIdx.x; i <= t; i += 256) m = fmaxf(m, p[i]);
    m = blk_max256(m, sh);
    float s = 0.f;
    for (int i = threadIdx.x; i <= t; i += 256) s += expf(p[i] - m);
    s = blk_sum256(s, sh);
    float inv = 1.0f / s;
    for (int i = threadIdx.x; i < TT; i += 256) {
        float o = 0.f;
        if (i <= t) {
            float pv = expf(p[i] - m) * inv;
            o = (pv >= thr) ? pv : 0.f;
        }
        p[i] = o;
    }
}

// ---------------- y = att @ v (per head), K clipped at causal boundary ----------------
__global__ __launch_bounds__(256) void attn_av_k() {
    int tt = blockIdx.x, h = blockIdx.y;
    int kh = h >> 2;
    __shared__ float As[16][65];
    __shared__ float Vs[16][64];
    int tid = threadIdx.x;
    int tx = tid & 15, ty = tid >> 4;
    float acc[4][4] = {};
    int kmax = (tt + 1) * 64;
    const float* abase = g_att + (size_t)h * TT * TT;
    for (int k0 = 0; k0 < kmax; k0 += 16) {
        #pragma unroll
        for (int i = 0; i < 4; i++) {
            int idx = tid + i * 256;
            int r = idx >> 4, c = idx & 15;
            As[c][r] = abase[(size_t)(tt * 64 + r) * TT + k0 + c];
        }
        #pragma unroll
        for (int i = 0; i < 4; i++) {
            int idx = tid + i * 256;
            int r = idx >> 6, c = idx & 63;
            Vs[r][c] = g_v[(size_t)(k0 + r) * KVD + kh * 64 + c];
        }
        __syncthreads();
        #pragma unroll
        for (int kk = 0; kk < 16; kk++) {
            float a[4], b[4];
            #pragma unroll
            for (int i = 0; i < 4; i++) a[i] = As[kk][ty * 4 + i];
            #pragma unroll
            for (int j = 0; j < 4; j++) b[j] = Vs[kk][tx * 4 + j];
            #pragma unroll
            for (int i = 0; i < 4; i++)
                #pragma unroll
                for (int j = 0; j < 4; j++)
                    acc[i][j] += a[i] * b[j];
        }
        __syncthreads();
    }
    #pragma unroll
    for (int i = 0; i < 4; i++)
        #pragma unroll
        for (int j = 0; j < 4; j++)
            g_y[(size_t)(tt * 64 + ty * 4 + i) * EE + h * 64 + tx * 4 + j] = acc[i][j];
}

// ---------------- loss ----------------
__global__ void zero_loss_k() { g_loss = 0.f; }

__global__ void loss_rows_k(const float* __restrict__ logits, const int* __restrict__ targets) {
    __shared__ float sh[256];
    int t = blockIdx.x;
    const float* row = logits + (size_t)t * VV;
    float m = -1e30f;
    for (int i = threadIdx.x; i < VV; i += 256) m = fmaxf(m, row[i]);
    m = blk_max256(m, sh);
    float s = 0.f;
    for (int i = threadIdx.x; i < VV; i += 256) s += expf(row[i] - m);
    s = blk_sum256(s, sh);
    if (threadIdx.x == 0) {
        float lp = row[targets[t]] - m - logf(s);
        atomicAdd(&g_loss, -lp);
    }
}

__global__ void loss_fin_k(float* dst) { *dst = g_loss * (1.0f / (float)TT); }

// ---------------- host orchestration ----------------
extern "C" void kernel_launch(void* const* d_in, const int* in_sizes, int n_in,
                              void* d_out, int out_size) {
    const float* embed = (const float*)d_in[0];
    const float* ln1_g = (const float*)d_in[1];
    const float* ln1_b = (const float*)d_in[2];
    const float* Wq    = (const float*)d_in[3];
    const float* Wk    = (const float*)d_in[4];
    const float* Wv    = (const float*)d_in[5];
    const float* Wo    = (const float*)d_in[6];
    const float* gate  = (const float*)d_in[7];
    const float* ln2_g = (const float*)d_in[8];
    const float* ln2_b = (const float*)d_in[9];
    const float* W1    = (const float*)d_in[10];
    const float* W2    = (const float*)d_in[11];
    const float* lnf_g = (const float*)d_in[12];
    const float* lnf_b = (const float*)d_in[13];
    const int*   idx   = (const int*)d_in[14];
    const int*   tgt   = (const int*)d_in[15];

    float *xp, *hp, *qp, *kp, *vp, *yp, *ffp, *logp, *lossp;
    cudaGetSymbolAddress((void**)&xp,   g_x);
    cudaGetSymbolAddress((void**)&hp,   g_h);
    cudaGetSymbolAddress((void**)&qp,   g_q);
    cudaGetSymbolAddress((void**)&kp,   g_k);
    cudaGetSymbolAddress((void**)&vp,   g_v);
    cudaGetSymbolAddress((void**)&yp,   g_y);
    cudaGetSymbolAddress((void**)&ffp,  g_ff);
    cudaGetSymbolAddress((void**)&logp, g_logits);
    cudaGetSymbolAddress((void**)&lossp, g_loss);

    const size_t BTV = (size_t)TT * VV;
    float* logits_dst = (out_size >= (int)BTV || (size_t)out_size >= BTV) ? (float*)d_out : logp;
    float* loss_dst = nullptr;
    if ((size_t)out_size > BTV)      loss_dst = (float*)d_out + BTV;
    else if ((size_t)out_size < BTV) loss_dst = (float*)d_out;   // loss-only output

    // embedding gather
    gather_embed_k<<<(TT * EE) / 256, 256>>>(embed, idx);

    for (int r = 0; r < RNUM; r++) {
        for (int l = 0; l < LNUM; l++) {
            const float* wq = Wq + (size_t)l * EE * EE;
            const float* wk = Wk + (size_t)l * EE * KVD;
            const float* wv = Wv + (size_t)l * EE * KVD;
            const float* wo = Wo + (size_t)l * EE * EE;
            const float* w1 = W1 + (size_t)l * EE * FF;
            const float* w2 = W2 + (size_t)l * FF * EE;

            // h = LN1(x)
            layernorm_k<<<TT, 256>>>(xp, hp, ln1_g + l * EE, ln1_b + l * EE);
            // q/k/v projections
            sgemm_k<0, false><<<dim3(EE / 128, TT / 128), 256>>>(hp, wq, qp, nullptr, TT, EE, EE);
            sgemm_k<0, false><<<dim3(KVD / 128, TT / 128), 256>>>(hp, wk, kp, nullptr, TT, KVD, EE);
            sgemm_k<0, false><<<dim3(KVD / 128, TT / 128), 256>>>(hp, wv, vp, nullptr, TT, KVD, EE);
            // RoPE
            rope_k<<<(TT * NH * 16) / 256, 256>>>(qp, NH);
            rope_k<<<(TT * NKV * 16) / 256, 256>>>(kp, NKV);
            // attention
            attn_scores_k<<<dim3(TT / 64, TT / 64, NH), 256>>>();
            softmax_thresh_k<<<NH * TT, 256>>>(gate, l);
            attn_av_k<<<dim3(TT / 64, NH), 256>>>();
            // x += y @ Wo
            sgemm_k<1, false><<<dim3(EE / 128, TT / 128), 256>>>(yp, wo, xp, xp, TT, EE, EE);
            // FFN
            layernorm_k<<<TT, 256>>>(xp, hp, ln2_g + l * EE, ln2_b + l * EE);
            sgemm_k<2, false><<<dim3(FF / 128, TT / 128), 256>>>(hp, w1, ffp, nullptr, TT, FF, EE);
            sgemm_k<1, false><<<dim3(EE / 128, TT / 128), 256>>>(ffp, w2, xp, xp, TT, EE, FF);
        }
    }

    // final LN + logits = h @ embed^T
    layernorm_k<<<TT, 256>>>(xp, hp, lnf_g, lnf_b);
    sgemm_k<0, true><<<dim3(VV / 128, TT / 128), 256>>>(hp, embed, logits_dst, nullptr, TT, VV, EE);

    // loss
    zero_loss_k<<<1, 1>>>();
    loss_rows_k<<<TT, 256>>>(logits_dst, tgt);
    if (loss_dst) loss_fin_k<<<1, 1>>>(loss_dst);
}